// round 1
// baseline (speedup 1.0000x reference)
#include <cuda_runtime.h>
#include <math.h>

#define DIMV     2880
#define SEQ      1024
#define NH       64
#define NKV      8
#define HD       64
#define QKVD     5120          // 64*80
#define QD       4096          // NH*HD
#define KDOFF    512           // NKV*HD
#define INTER    2880
#define NEXP     4
#define LIMITF   7.0f
#define ALPHAF   1.702f
#define SM_SCALE 0.125f        // 1/sqrt(64)

// ---------------- scratch (device globals; no allocation) ----------------
__device__ float g_t[SEQ * DIMV];
__device__ float g_qkv[SEQ * QKVD];
__device__ float g_attn[SEQ * QD];
__device__ float g_act[NEXP * SEQ * INTER];
__device__ float g_cos[SEQ * 32];
__device__ float g_sin[SEQ * 32];
__device__ int   g_sel[SEQ * 2];
__device__ float g_selw[SEQ * 2];
__device__ int   g_list[NEXP * SEQ];
__device__ float g_wgt[NEXP * SEQ];
__device__ int   g_cnt[NEXP];

// ---------------- YaRN tables (double precision, once) ----------------
__global__ void yarn_k(float* __restrict__ cosT, float* __restrict__ sinT) {
    int pos = blockIdx.x;
    int d   = threadIdx.x;  // 0..31
    double freq   = pow(150000.0, (double)d / 32.0);
    double interp = 1.0 / (32.0 * freq);
    double extrap = 1.0 / freq;
    double low  = 32.0 * log(4096.0 / (32.0 * 2.0 * M_PI)) / log(150000.0);
    double high = 32.0 * log(4096.0 / ( 1.0 * 2.0 * M_PI)) / log(150000.0);
    double ramp = ((double)d - low) / (high - low);
    double mm   = 1.0 - fmin(fmax(ramp, 0.0), 1.0);
    double inv  = interp * (1.0 - mm) + extrap * mm;
    double conc = 0.1 * log(32.0) + 1.0;
    double fr   = (double)pos * inv;
    cosT[pos * 32 + d] = (float)(cos(fr) * conc);
    sinT[pos * 32 + d] = (float)(sin(fr) * conc);
}

// ---------------- RMSNorm ----------------
__global__ void rmsnorm_k(const float* __restrict__ x, const float* __restrict__ w,
                          float* __restrict__ o) {
    int t = blockIdx.x, tid = threadIdx.x;
    __shared__ float red[256];
    const float* xr = x + (size_t)t * DIMV;
    float s = 0.f;
    for (int i = tid; i < DIMV; i += 256) { float v = xr[i]; s += v * v; }
    red[tid] = s; __syncthreads();
    for (int off = 128; off > 0; off >>= 1) {
        if (tid < off) red[tid] += red[tid + off];
        __syncthreads();
    }
    float inv = 1.0f / sqrtf(red[0] / (float)DIMV + 1e-5f);
    float* orow = o + (size_t)t * DIMV;
    for (int i = tid; i < DIMV; i += 256) orow[i] = xr[i] * inv * w[i];
}

// ---------------- RoPE (in place on qkv) ----------------
__global__ void rope_k(float* __restrict__ qkv, const float* __restrict__ cosT,
                       const float* __restrict__ sinT) {
    int pos = blockIdx.x;
    int hh  = blockIdx.y;           // 0..63 q heads, 64..71 k heads
    int d   = threadIdx.x;          // 0..31
    int col = (hh < NH) ? hh * HD : QD + (hh - NH) * HD;
    float c = cosT[pos * 32 + d];
    float s = sinT[pos * 32 + d];
    float* p = qkv + (size_t)pos * QKVD + col;
    float x1 = p[d], x2 = p[d + 32];
    p[d]      = x1 * c - x2 * s;
    p[d + 32] = x2 * c + x1 * s;
}

// ---------------- Attention: 32 queries x 1 head per block ----------------
__global__ __launch_bounds__(128) void attn_k(const float* __restrict__ qkv,
                                              const float* __restrict__ sinks,
                                              float* __restrict__ out, int window) {
    __shared__ float q_s[32][65];
    __shared__ float kv_s[64][65];
    __shared__ float p_s[32][65];
    __shared__ float scale_s[32];

    int qb = blockIdx.x, h = blockIdx.y;
    int q0 = qb * 32;
    int kvh = h >> 3;
    int tid = threadIdx.x;
    int r0 = (tid >> 4) * 4;      // 4 query rows per thread
    int c0 = (tid & 15) * 4;      // 4 key-cols / dim-cols per thread

    // load Q tile
    for (int idx = tid; idx < 32 * 16; idx += 128) {
        int row = idx >> 4, c4 = (idx & 15) * 4;
        float4 v = *(const float4*)&qkv[(size_t)(q0 + row) * QKVD + h * HD + c4];
        q_s[row][c4] = v.x; q_s[row][c4 + 1] = v.y; q_s[row][c4 + 2] = v.z; q_s[row][c4 + 3] = v.w;
    }

    float m = 0.f, l = 0.f;
    if (tid < 32) { m = sinks[h]; l = 1.0f; }   // sink folded into softmax state
    float acc[4][4];
#pragma unroll
    for (int i = 0; i < 4; i++)
#pragma unroll
        for (int j = 0; j < 4; j++) acc[i][j] = 0.f;

    int jlo = 0;
    if (window > 0) { jlo = q0 - window + 1; if (jlo < 0) jlo = 0; }
    int kcol = QD + kvh * HD;
    int vcol = QD + KDOFF + kvh * HD;

    for (int t0 = (jlo >> 6) << 6; t0 <= q0 + 31; t0 += 64) {
        __syncthreads();  // kv_s reuse barrier
        // load K tile
        for (int idx = tid; idx < 64 * 16; idx += 128) {
            int row = idx >> 4, c4 = (idx & 15) * 4;
            float4 v = *(const float4*)&qkv[(size_t)(t0 + row) * QKVD + kcol + c4];
            kv_s[row][c4] = v.x; kv_s[row][c4 + 1] = v.y; kv_s[row][c4 + 2] = v.z; kv_s[row][c4 + 3] = v.w;
        }
        __syncthreads();

        // scores (4x4 per thread)
        float sc[4][4];
#pragma unroll
        for (int i = 0; i < 4; i++)
#pragma unroll
            for (int j = 0; j < 4; j++) sc[i][j] = 0.f;
#pragma unroll 8
        for (int kk = 0; kk < 64; kk++) {
            float qa[4], kb[4];
#pragma unroll
            for (int i = 0; i < 4; i++) qa[i] = q_s[r0 + i][kk];
#pragma unroll
            for (int j = 0; j < 4; j++) kb[j] = kv_s[c0 + j][kk];
#pragma unroll
            for (int i = 0; i < 4; i++)
#pragma unroll
                for (int j = 0; j < 4; j++) sc[i][j] += qa[i] * kb[j];
        }
#pragma unroll
        for (int i = 0; i < 4; i++)
#pragma unroll
            for (int j = 0; j < 4; j++) {
                int ii = q0 + r0 + i, jj = t0 + c0 + j;
                bool ok = (jj <= ii) && (window == 0 || (ii - jj) < window);
                p_s[r0 + i][c0 + j] = ok ? sc[i][j] * SM_SCALE : -1e30f;
            }
        __syncthreads();

        // online softmax, one thread per row
        if (tid < 32) {
            int r = tid;
            float mn = m;
            for (int j = 0; j < 64; j++) mn = fmaxf(mn, p_s[r][j]);
            float rs = __expf(m - mn);
            float sum = 0.f;
            for (int j = 0; j < 64; j++) {
                float e = __expf(p_s[r][j] - mn);
                p_s[r][j] = e; sum += e;
            }
            l = l * rs + sum; m = mn;
            scale_s[r] = rs;
        }
        __syncthreads();

        // rescale accumulators
#pragma unroll
        for (int i = 0; i < 4; i++) {
            float s = scale_s[r0 + i];
#pragma unroll
            for (int k = 0; k < 4; k++) acc[i][k] *= s;
        }
        // load V tile (K consumed)
        for (int idx = tid; idx < 64 * 16; idx += 128) {
            int row = idx >> 4, c4 = (idx & 15) * 4;
            float4 v = *(const float4*)&qkv[(size_t)(t0 + row) * QKVD + vcol + c4];
            kv_s[row][c4] = v.x; kv_s[row][c4 + 1] = v.y; kv_s[row][c4 + 2] = v.z; kv_s[row][c4 + 3] = v.w;
        }
        __syncthreads();

        // P @ V
#pragma unroll 8
        for (int j = 0; j < 64; j++) {
            float pv[4], vv[4];
#pragma unroll
            for (int i = 0; i < 4; i++) pv[i] = p_s[r0 + i][j];
#pragma unroll
            for (int k = 0; k < 4; k++) vv[k] = kv_s[j][c0 + k];
#pragma unroll
            for (int i = 0; i < 4; i++)
#pragma unroll
                for (int k = 0; k < 4; k++) acc[i][k] += pv[i] * vv[k];
        }
    }
    __syncthreads();
    if (tid < 32) scale_s[tid] = 1.0f / l;
    __syncthreads();
#pragma unroll
    for (int i = 0; i < 4; i++) {
        float li = scale_s[r0 + i];
#pragma unroll
        for (int k = 0; k < 4; k++)
            out[(size_t)(q0 + r0 + i) * QD + h * HD + c0 + k] = acc[i][k] * li;
    }
}

// ---------------- gate logits + top-2 softmax ----------------
__global__ void gate_k(const float* __restrict__ t, const float* __restrict__ gw,
                       const float* __restrict__ gb, int* __restrict__ sel,
                       float* __restrict__ selw) {
    int tk = blockIdx.x, tid = threadIdx.x;  // 128 threads
    __shared__ float red[4][128];
    float p[4] = {0.f, 0.f, 0.f, 0.f};
    const float* tr = t + (size_t)tk * DIMV;
    for (int k = tid; k < DIMV; k += 128) {
        float v = tr[k];
#pragma unroll
        for (int e = 0; e < 4; e++) p[e] += v * gw[k * 4 + e];
    }
#pragma unroll
    for (int e = 0; e < 4; e++) red[e][tid] = p[e];
    __syncthreads();
    for (int off = 64; off > 0; off >>= 1) {
        if (tid < off)
#pragma unroll
            for (int e = 0; e < 4; e++) red[e][tid] += red[e][tid + off];
        __syncthreads();
    }
    if (tid == 0) {
        float v[4];
#pragma unroll
        for (int e = 0; e < 4; e++) v[e] = red[e][0] + gb[e];
        int i0 = 0;
        for (int e = 1; e < 4; e++) if (v[e] > v[i0]) i0 = e;
        int i1 = (i0 == 0) ? 1 : 0;
        for (int e = 0; e < 4; e++) if (e != i0 && v[e] > v[i1]) i1 = e;
        float ex = expf(v[i1] - v[i0]);
        float den = 1.0f + ex;
        sel[tk * 2] = i0; sel[tk * 2 + 1] = i1;
        selw[tk * 2] = 1.0f / den; selw[tk * 2 + 1] = ex / den;
    }
}

// ---------------- deterministic expert list builder (1 warp / expert) -------
__global__ void build_lists_k(const int* __restrict__ sel, const float* __restrict__ selw,
                              int* __restrict__ list, float* __restrict__ wgt,
                              int* __restrict__ cnt) {
    int w = threadIdx.x >> 5, lane = threadIdx.x & 31;
    if (w >= NEXP) return;
    int e = w, c = 0;
    for (int base = 0; base < SEQ; base += 32) {
        int tk = base + lane;
        int s0 = sel[tk * 2], s1 = sel[tk * 2 + 1];
        bool f = (s0 == e) || (s1 == e);
        float wv = (s0 == e) ? selw[tk * 2] : selw[tk * 2 + 1];
        unsigned msk = __ballot_sync(0xffffffffu, f);
        if (f) {
            int pos = c + __popc(msk & ((1u << lane) - 1u));
            list[e * SEQ + pos] = tk;
            wgt[e * SEQ + pos]  = wv;
        }
        c += __popc(msk);
    }
    if (lane == 0) cnt[e] = c;
}

// ---------------- generic 128x128x8 SGEMM, 4 epilogues ----------------
// MODE 0: C = A@B + bias
// MODE 1: X += A@B + bias                        (residual add)
// MODE 2: A rows gathered via rowlist (tokens); h = A@B + bias; fused
//         clipped-SwiGLU pairing -> C (act, leading dim INTER)
// MODE 3: X[token] += roww * (A@B + bias)        (scatter residual add)
template <int MODE>
__global__ __launch_bounds__(256, 2) void sgemm_k(
    const float* __restrict__ A, const float* __restrict__ B,
    const float* __restrict__ bias, float* __restrict__ C,
    int M, int N, int K,
    const int* __restrict__ rowlist, const float* __restrict__ roww,
    const int* __restrict__ cntp, float* __restrict__ X) {
    __shared__ float As[8][128];
    __shared__ float Bs[8][128];

    int Meff = M;
    if (MODE == 2 || MODE == 3) {
        Meff = *cntp;
        if ((int)blockIdx.y * 128 >= Meff) return;
    }
    int row0 = blockIdx.y * 128;
    int n0   = blockIdx.x * 128;
    int tid  = threadIdx.x;

    int a_row = tid >> 1, a_kc = (tid & 1) * 4;
    int b_row = tid >> 5, b_col = (tid & 31) * 4;

    int arow_g = row0 + a_row;
    bool avalid = arow_g < Meff;
    int asrc = 0;
    if (MODE == 2) asrc = avalid ? rowlist[arow_g] : 0;
    else           asrc = avalid ? arow_g : 0;
    const float* Aptr = A + (size_t)asrc * K + a_kc;
    const float* Bptr = B + n0 + b_col;
    bool bvalid = (n0 + b_col) < N;

    int ty = tid >> 4, tx = tid & 15;
    float acc[8][8];
#pragma unroll
    for (int i = 0; i < 8; i++)
#pragma unroll
        for (int j = 0; j < 8; j++) acc[i][j] = 0.f;

    for (int k0 = 0; k0 < K; k0 += 8) {
        float4 av = avalid ? *(const float4*)(Aptr + k0) : make_float4(0.f, 0.f, 0.f, 0.f);
        As[a_kc + 0][a_row] = av.x; As[a_kc + 1][a_row] = av.y;
        As[a_kc + 2][a_row] = av.z; As[a_kc + 3][a_row] = av.w;
        float4 bv = bvalid ? *(const float4*)(Bptr + (size_t)(k0 + b_row) * N)
                           : make_float4(0.f, 0.f, 0.f, 0.f);
        *(float4*)&Bs[b_row][b_col] = bv;
        __syncthreads();
#pragma unroll
        for (int k = 0; k < 8; k++) {
            float a[8], b[8];
            *(float4*)(a)     = *(const float4*)&As[k][ty * 8];
            *(float4*)(a + 4) = *(const float4*)&As[k][ty * 8 + 4];
            *(float4*)(b)     = *(const float4*)&Bs[k][tx * 8];
            *(float4*)(b + 4) = *(const float4*)&Bs[k][tx * 8 + 4];
#pragma unroll
            for (int i = 0; i < 8; i++)
#pragma unroll
                for (int j = 0; j < 8; j++) acc[i][j] += a[i] * b[j];
        }
        __syncthreads();
    }

#pragma unroll
    for (int i = 0; i < 8; i++) {
        int r = row0 + ty * 8 + i;
        if (r >= Meff) continue;
        if (MODE == 0) {
#pragma unroll
            for (int j = 0; j < 8; j++) {
                int c = n0 + tx * 8 + j;
                if (c < N) C[(size_t)r * N + c] = acc[i][j] + bias[c];
            }
        } else if (MODE == 1) {
#pragma unroll
            for (int j = 0; j < 8; j++) {
                int c = n0 + tx * 8 + j;
                if (c < N) X[(size_t)r * N + c] += acc[i][j] + bias[c];
            }
        } else if (MODE == 2) {
#pragma unroll
            for (int j = 0; j < 8; j += 2) {
                int c = n0 + tx * 8 + j;
                if (c < N) {
                    float h0 = acc[i][j]     + bias[c];
                    float h1 = acc[i][j + 1] + bias[c + 1];
                    float glu = fminf(h0, LIMITF);
                    float lin = fminf(fmaxf(h1, -LIMITF), LIMITF);
                    float a = glu * (1.0f / (1.0f + expf(-ALPHAF * glu))) * (lin + 1.0f);
                    C[(size_t)r * INTER + (c >> 1)] = a;
                }
            }
        } else {  // MODE 3
            int tk = rowlist[r];
            float w = roww[r];
#pragma unroll
            for (int j = 0; j < 8; j++) {
                int c = n0 + tx * 8 + j;
                if (c < N) X[(size_t)tk * DIMV + c] += w * (acc[i][j] + bias[c]);
            }
        }
    }
}

// ---------------- host ----------------
extern "C" void kernel_launch(void* const* d_in, const int* in_sizes, int n_in,
                              void* d_out, int out_size) {
    const float* x_in   = (const float*)d_in[0];
    const float* rms1w  = (const float*)d_in[1];
    const float* qkvw   = (const float*)d_in[2];
    const float* qkvb   = (const float*)d_in[3];
    const float* outw   = (const float*)d_in[4];
    const float* outb   = (const float*)d_in[5];
    const float* sinks  = (const float*)d_in[6];
    const float* rms2w  = (const float*)d_in[7];
    const float* gatew  = (const float*)d_in[8];
    const float* gateb  = (const float*)d_in[9];
    const float* w1     = (const float*)d_in[10];
    const float* b1     = (const float*)d_in[11];
    const float* w2     = (const float*)d_in[12];
    const float* b2     = (const float*)d_in[13];

    float *t, *qkv, *attn, *act, *cosT, *sinT, *selw, *wgt;
    int *sel, *list, *cnt;
    cudaGetSymbolAddress((void**)&t,    g_t);
    cudaGetSymbolAddress((void**)&qkv,  g_qkv);
    cudaGetSymbolAddress((void**)&attn, g_attn);
    cudaGetSymbolAddress((void**)&act,  g_act);
    cudaGetSymbolAddress((void**)&cosT, g_cos);
    cudaGetSymbolAddress((void**)&sinT, g_sin);
    cudaGetSymbolAddress((void**)&sel,  g_sel);
    cudaGetSymbolAddress((void**)&selw, g_selw);
    cudaGetSymbolAddress((void**)&list, g_list);
    cudaGetSymbolAddress((void**)&wgt,  g_wgt);
    cudaGetSymbolAddress((void**)&cnt,  g_cnt);

    float* X = (float*)d_out;
    cudaMemcpyAsync(X, x_in, sizeof(float) * SEQ * DIMV, cudaMemcpyDeviceToDevice);

    yarn_k<<<SEQ, 32>>>(cosT, sinT);

    for (int layer = 0; layer < 2; layer++) {
        // attention sub-block
        rmsnorm_k<<<SEQ, 256>>>(X, rms1w + (size_t)layer * DIMV, t);
        sgemm_k<0><<<dim3(QKVD / 128, SEQ / 128), 256>>>(
            t, qkvw + (size_t)layer * DIMV * QKVD, qkvb + (size_t)layer * QKVD, qkv,
            SEQ, QKVD, DIMV, nullptr, nullptr, nullptr, nullptr);
        rope_k<<<dim3(SEQ, NH + NKV), 32>>>(qkv, cosT, sinT);
        attn_k<<<dim3(SEQ / 32, NH), 128>>>(qkv, sinks + (size_t)layer * NH, attn,
                                            (layer % 2 == 0) ? 128 : 0);
        sgemm_k<1><<<dim3((DIMV + 127) / 128, SEQ / 128), 256>>>(
            attn, outw + (size_t)layer * QD * DIMV, outb + (size_t)layer * DIMV, nullptr,
            SEQ, DIMV, QD, nullptr, nullptr, nullptr, X);

        // MoE sub-block
        rmsnorm_k<<<SEQ, 256>>>(X, rms2w + (size_t)layer * DIMV, t);
        gate_k<<<SEQ, 128>>>(t, gatew + (size_t)layer * DIMV * NEXP,
                             gateb + (size_t)layer * NEXP, sel, selw);
        build_lists_k<<<1, 128>>>(sel, selw, list, wgt, cnt);
        for (int e = 0; e < NEXP; e++) {
            sgemm_k<2><<<dim3((2 * INTER) / 128, SEQ / 128), 256>>>(
                t, w1 + ((size_t)layer * NEXP + e) * DIMV * 2 * INTER,
                b1 + ((size_t)layer * NEXP + e) * 2 * INTER,
                act + (size_t)e * SEQ * INTER,
                0, 2 * INTER, DIMV, list + e * SEQ, nullptr, cnt + e, nullptr);
        }
        for (int e = 0; e < NEXP; e++) {
            sgemm_k<3><<<dim3((DIMV + 127) / 128, SEQ / 128), 256>>>(
                act + (size_t)e * SEQ * INTER,
                w2 + ((size_t)layer * NEXP + e) * INTER * DIMV,
                b2 + ((size_t)layer * NEXP + e) * DIMV, nullptr,
                0, DIMV, INTER, list + e * SEQ, wgt + e * SEQ, cnt + e, X);
        }
    }
    (void)in_sizes; (void)n_in; (void)out_size;
}